// round 15
// baseline (speedup 1.0000x reference)
#include <cuda_runtime.h>
#include <cuda_fp16.h>
#include <math.h>

#define N_NODES 100000
#define N_EDGES_MAX 3200000
#define N_GRAPHS 512
#define D_FEAT 128
#define D_HID 32
#define SCAN_B 512
#define NB_SCAN ((N_NODES + SCAN_B - 1) / SCAN_B)   // 196

// Scratch (allocation-free rule: __device__ globals; referenced ONLY in device code)
__device__ __align__(16) __half d_Ah[N_NODES * D_HID];   // fp16 feature ping
__device__ __align__(16) __half d_Bh[N_NODES * D_HID];   // fp16 feature pong
__device__ float d_pool[N_GRAPHS * D_HID];
__device__ int d_deg[N_NODES];
__device__ int d_off[N_NODES + 1];
__device__ int d_cur[N_NODES];
__device__ int d_bsum[NB_SCAN];
__device__ __align__(8) float2 d_pk[N_EDGES_MAX];   // (col bits, w) grouped by row

__device__ __forceinline__ float elu_f(float x) { return x > 0.f ? x : expm1f(x); }

// ---------------------------------------------------------------------------
// Layer 1 projection: d_Ah = fp16(x @ W1)   (x: [N,128], W1: [128,32])
// ---------------------------------------------------------------------------
__global__ void __launch_bounds__(128) proj1_kernel(const float* __restrict__ x,
                                                    const float* __restrict__ W) {
    __shared__ float sW[D_FEAT * D_HID];
    for (int i = threadIdx.x; i < D_FEAT * D_HID; i += 128) sW[i] = W[i];
    __syncthreads();

    int n = blockIdx.x * 128 + threadIdx.x;
    if (n >= N_NODES) return;

    float acc[D_HID];
#pragma unroll
    for (int j = 0; j < D_HID; j++) acc[j] = 0.f;

    const float4* xr = reinterpret_cast<const float4*>(x) + (size_t)n * (D_FEAT / 4);
#pragma unroll 4
    for (int k4 = 0; k4 < D_FEAT / 4; k4++) {
        float4 v = xr[k4];
        const float* w0 = &sW[(k4 * 4 + 0) * D_HID];
        const float* w1 = &sW[(k4 * 4 + 1) * D_HID];
        const float* w2 = &sW[(k4 * 4 + 2) * D_HID];
        const float* w3 = &sW[(k4 * 4 + 3) * D_HID];
#pragma unroll
        for (int j = 0; j < D_HID; j++)
            acc[j] += v.x * w0[j] + v.y * w1[j] + v.z * w2[j] + v.w * w3[j];
    }

    __half2* out2 = reinterpret_cast<__half2*>(d_Ah) + (size_t)n * (D_HID / 2);
#pragma unroll
    for (int q = 0; q < D_HID / 2; q++)
        out2[q] = __floats2half2_rn(acc[2 * q], acc[2 * q + 1]);
}

// ---------------------------------------------------------------------------
// CSR build (coalesced 3-stage scan — the proven-fast structure)
// ---------------------------------------------------------------------------
__global__ void __launch_bounds__(256) zero_misc_kernel() {
    int i = blockIdx.x * 256 + threadIdx.x;
    if (i < N_NODES) d_deg[i] = 0;
    if (i < N_GRAPHS * D_HID) d_pool[i] = 0.f;
}

__global__ void __launch_bounds__(256) count_kernel(const int* __restrict__ row, int E) {
    int e = blockIdx.x * 256 + threadIdx.x;
    if (e < E) atomicAdd(&d_deg[row[e]], 1);
}

__global__ void __launch_bounds__(SCAN_B) scan1_kernel() {
    __shared__ int sh[SCAN_B];
    int i = blockIdx.x * SCAN_B + threadIdx.x;
    int v = (i < N_NODES) ? d_deg[i] : 0;
    sh[threadIdx.x] = v;
    __syncthreads();
    for (int s = 1; s < SCAN_B; s <<= 1) {
        int t = (threadIdx.x >= s) ? sh[threadIdx.x - s] : 0;
        __syncthreads();
        sh[threadIdx.x] += t;
        __syncthreads();
    }
    if (i < N_NODES) d_off[i] = sh[threadIdx.x] - v;   // exclusive
    if (threadIdx.x == SCAN_B - 1) d_bsum[blockIdx.x] = sh[SCAN_B - 1];
}

__global__ void __launch_bounds__(256) scan2_kernel() {
    __shared__ int sh[256];
    int v = (threadIdx.x < NB_SCAN) ? d_bsum[threadIdx.x] : 0;
    sh[threadIdx.x] = v;
    __syncthreads();
    for (int s = 1; s < 256; s <<= 1) {
        int t = (threadIdx.x >= s) ? sh[threadIdx.x - s] : 0;
        __syncthreads();
        sh[threadIdx.x] += t;
        __syncthreads();
    }
    if (threadIdx.x < NB_SCAN) d_bsum[threadIdx.x] = sh[threadIdx.x] - v;  // exclusive
}

__global__ void __launch_bounds__(SCAN_B) scan3_kernel(int E) {
    int i = blockIdx.x * SCAN_B + threadIdx.x;
    if (i < N_NODES) {
        int o = d_off[i] + d_bsum[blockIdx.x];
        d_off[i] = o;
        d_cur[i] = o;
    }
    if (i == 0) d_off[N_NODES] = E;
}

__global__ void __launch_bounds__(256) fill_kernel(const int* __restrict__ row,
                                                   const int* __restrict__ col,
                                                   const float* __restrict__ ew, int E) {
    int e = blockIdx.x * 256 + threadIdx.x;
    if (e >= E) return;
    int r = row[e];
    int pos = atomicAdd(&d_cur[r], 1);
    d_pk[pos] = make_float2(__int_as_float(col[e]), ew[e]);
}

// ---------------------------------------------------------------------------
// Fused SpMM gather: warp per node, 4 edges per LDG.64, fp16 src / fp32 accum.
// Lanes split into 4 groups of 8; group g handles edge e+g; lane s (0-7)
// loads uint2 = 4 halfs = cols 4s..4s+3 of that edge's source row (64B/row).
// Cross-group reduce via shfl_xor(8|16).
//   PASS 0: src=d_Ah, dst=d_Bh, PROJ (elu(acc+b) @ W, fp16 out)
//   PASS 1: src=d_Bh, dst=d_Ah, PROJ
//   PASS 2: src=d_Ah, fused pool: red.global d_pool[seg[n]] += elu(acc+b)
// ---------------------------------------------------------------------------
template <int PASS, bool PROJ>
__global__ void __launch_bounds__(256) spmm4h_kernel(const float* __restrict__ W,
                                                     const float* __restrict__ b,
                                                     const int* __restrict__ seg) {
    const uint2* __restrict__ src =
        reinterpret_cast<const uint2*>((PASS == 1) ? d_Bh : d_Ah);

    __shared__ float sW[D_HID * D_HID];
    __shared__ float sb[D_HID];
    if (PROJ)
        for (int i = threadIdx.x; i < D_HID * D_HID; i += 256) sW[i] = W[i];
    if (threadIdx.x < D_HID) sb[threadIdx.x] = b[threadIdx.x];
    __syncthreads();

    int wid = blockIdx.x * 8 + (threadIdx.x >> 5);
    if (wid >= N_NODES) return;
    int lane = threadIdx.x & 31;
    int s = lane & 7;        // 4-half slot within row
    int g = lane >> 3;       // edge group 0..3

    int beg = d_off[wid];
    int end = d_off[wid + 1];

    float ax = 0.f, ay = 0.f, az = 0.f, aw = 0.f;
    int e = beg;

    // 8 edges per iteration: two independent LDG.64 chains in flight
    for (; e + 8 <= end; e += 8) {
        float2 pa = d_pk[e + g];
        float2 pb = d_pk[e + 4 + g];
        uint2 ua = src[(size_t)__float_as_int(pa.x) * 8 + s];
        uint2 ub = src[(size_t)__float_as_int(pb.x) * 8 + s];
        float2 a0 = __half22float2(*reinterpret_cast<__half2*>(&ua.x));
        float2 a1 = __half22float2(*reinterpret_cast<__half2*>(&ua.y));
        float2 b0 = __half22float2(*reinterpret_cast<__half2*>(&ub.x));
        float2 b1 = __half22float2(*reinterpret_cast<__half2*>(&ub.y));
        ax += pa.y * a0.x; ay += pa.y * a0.y; az += pa.y * a1.x; aw += pa.y * a1.y;
        ax += pb.y * b0.x; ay += pb.y * b0.y; az += pb.y * b1.x; aw += pb.y * b1.y;
    }
    for (; e + 4 <= end; e += 4) {
        float2 p = d_pk[e + g];
        uint2 u = src[(size_t)__float_as_int(p.x) * 8 + s];
        float2 v0 = __half22float2(*reinterpret_cast<__half2*>(&u.x));
        float2 v1 = __half22float2(*reinterpret_cast<__half2*>(&u.y));
        ax += p.y * v0.x; ay += p.y * v0.y; az += p.y * v1.x; aw += p.y * v1.y;
    }
    int rem = end - e;
    if (rem > 0) {
        float2 p = d_pk[e + (g < rem ? g : 0)];
        float wgt = (g < rem) ? p.y : 0.f;
        uint2 u = src[(size_t)__float_as_int(p.x) * 8 + s];
        float2 v0 = __half22float2(*reinterpret_cast<__half2*>(&u.x));
        float2 v1 = __half22float2(*reinterpret_cast<__half2*>(&u.y));
        ax += wgt * v0.x; ay += wgt * v0.y; az += wgt * v1.x; aw += wgt * v1.y;
    }

    // reduce the 4 edge-groups
    ax += __shfl_xor_sync(0xffffffffu, ax, 8);
    ay += __shfl_xor_sync(0xffffffffu, ay, 8);
    az += __shfl_xor_sync(0xffffffffu, az, 8);
    aw += __shfl_xor_sync(0xffffffffu, aw, 8);
    ax += __shfl_xor_sync(0xffffffffu, ax, 16);
    ay += __shfl_xor_sync(0xffffffffu, ay, 16);
    az += __shfl_xor_sync(0xffffffffu, az, 16);
    aw += __shfl_xor_sync(0xffffffffu, aw, 16);

    // every lane with slot s now holds full sums of cols 4s..4s+3
    float hv[4];
    hv[0] = elu_f(ax + sb[4 * s + 0]);
    hv[1] = elu_f(ay + sb[4 * s + 1]);
    hv[2] = elu_f(az + sb[4 * s + 2]);
    hv[3] = elu_f(aw + sb[4 * s + 3]);

    if (PROJ) {
        // h_k lives in lane k/4 (lanes 0-7), component k%4 (compile-time index)
        float o = 0.f;
#pragma unroll
        for (int k = 0; k < D_HID; k++) {
            float hk = __shfl_sync(0xffffffffu, hv[k & 3], k >> 2);
            o += hk * sW[k * D_HID + lane];
        }
        __half* dst = (PASS == 0) ? d_Bh : d_Ah;
        dst[(size_t)wid * D_HID + lane] = __float2half_rn(o);
    } else {
        // fused global pool: one v4 reduction per slot, group-0 lanes only
        if (g == 0) {
            int gr = seg[wid];
            float* p = &d_pool[gr * D_HID + 4 * s];
            asm volatile("red.global.add.v4.f32 [%0], {%1, %2, %3, %4};"
                         :: "l"(p), "f"(hv[0]), "f"(hv[1]), "f"(hv[2]), "f"(hv[3])
                         : "memory");
        }
    }
}

// ---------------------------------------------------------------------------
// Dense head
// ---------------------------------------------------------------------------
__global__ void __launch_bounds__(64) mlp_kernel(const float* __restrict__ Wd1,
                                                 const float* __restrict__ bd1,
                                                 const float* __restrict__ Wd2,
                                                 const float* __restrict__ bd2,
                                                 const float* __restrict__ Wd3,
                                                 const float* __restrict__ bd3,
                                                 float* __restrict__ out) {
    __shared__ float sW1[32 * 64];
    __shared__ float sW2[64 * 32];
    __shared__ float sW3[32];
    __shared__ float sg[32];
    __shared__ float sh1[64];
    __shared__ float sh2[32];

    int t = threadIdx.x;
    int r = blockIdx.x;
    for (int i = t; i < 32 * 64; i += 64) sW1[i] = Wd1[i];
    for (int i = t; i < 64 * 32; i += 64) sW2[i] = Wd2[i];
    if (t < 32) sW3[t] = Wd3[t];
    if (t < 32) sg[t] = d_pool[r * 32 + t];
    __syncthreads();

    {
        float a = bd1[t];
#pragma unroll
        for (int k = 0; k < 32; k++) a += sg[k] * sW1[k * 64 + t];
        sh1[t] = fmaxf(a, 0.f);
    }
    __syncthreads();

    if (t < 32) {
        float a = bd2[t];
#pragma unroll
        for (int k = 0; k < 64; k++) a += sh1[k] * sW2[k * 32 + t];
        sh2[t] = fmaxf(a, 0.f);
    }
    __syncthreads();

    if (t == 0) {
        float a = bd3[0];
#pragma unroll
        for (int k = 0; k < 32; k++) a += sh2[k] * sW3[k];
        out[r] = 1.f / (1.f + expf(-a));
    }
}

// ---------------------------------------------------------------------------
// Launch
// ---------------------------------------------------------------------------
extern "C" void kernel_launch(void* const* d_in, const int* in_sizes, int n_in,
                              void* d_out, int out_size) {
    const float* x   = (const float*)d_in[0];
    const int*   ei  = (const int*)d_in[1];
    const float* ew  = (const float*)d_in[2];
    const int*   seg = (const int*)d_in[3];
    const float* W1  = (const float*)d_in[4];
    const float* b1  = (const float*)d_in[5];
    const float* W2  = (const float*)d_in[6];
    const float* b2  = (const float*)d_in[7];
    const float* W3  = (const float*)d_in[8];
    const float* b3  = (const float*)d_in[9];
    const float* Wd1 = (const float*)d_in[10];
    const float* bd1 = (const float*)d_in[11];
    const float* Wd2 = (const float*)d_in[12];
    const float* bd2 = (const float*)d_in[13];
    const float* Wd3 = (const float*)d_in[14];
    const float* bd3 = (const float*)d_in[15];
    float* out = (float*)d_out;

    int E = in_sizes[2];
    const int* row = ei;
    const int* col = ei + E;

    const int egrid = (E + 255) / 256;
    const int ggrid = (N_NODES + 7) / 8;        // warp-per-node

    // CSR build (+ zero the pool table)
    zero_misc_kernel<<<(N_NODES + 255) / 256, 256>>>();
    count_kernel<<<egrid, 256>>>(row, E);
    scan1_kernel<<<NB_SCAN, SCAN_B>>>();
    scan2_kernel<<<1, 256>>>();
    scan3_kernel<<<NB_SCAN, SCAN_B>>>(E);
    fill_kernel<<<egrid, 256>>>(row, col, ew, E);

    // Layer 1 projection (fp16 out)
    proj1_kernel<<<(N_NODES + 127) / 128, 128>>>(x, W1);

    // Fused SpMM + elu + projection chain (fp16 features, fp32 accumulate)
    spmm4h_kernel<0, true><<<ggrid, 256>>>(W2, b1, nullptr);   // Ah -> Bh
    spmm4h_kernel<1, true><<<ggrid, 256>>>(W3, b2, nullptr);   // Bh -> Ah
    spmm4h_kernel<2, false><<<ggrid, 256>>>(nullptr, b3, seg); // Ah -> pool

    // Dense head
    mlp_kernel<<<N_GRAPHS, 64>>>(Wd1, bd1, Wd2, bd2, Wd3, bd3, out);
}

// round 17
// speedup vs baseline: 1.0065x; 1.0065x over previous
#include <cuda_runtime.h>
#include <math.h>

#define N_NODES 100000
#define N_EDGES_MAX 3200000
#define N_GRAPHS 512
#define D_FEAT 128
#define D_HID 32
#define SCAN_B 512
#define NB_SCAN ((N_NODES + SCAN_B - 1) / SCAN_B)   // 196

// Scratch (allocation-free rule: __device__ globals; referenced ONLY in device code)
__device__ __align__(16) float d_A[N_NODES * D_HID];
__device__ __align__(16) float d_B[N_NODES * D_HID];
__device__ float d_pool[N_GRAPHS * D_HID];
__device__ int d_deg[N_NODES];
__device__ int d_off[N_NODES + 1];
__device__ int d_cur[N_NODES];
__device__ int d_bsum[NB_SCAN];
__device__ __align__(8) float2 d_pk[N_EDGES_MAX];   // (col bits, w) grouped by row

__device__ __forceinline__ float elu_f(float x) { return x > 0.f ? x : expm1f(x); }

// ---------------------------------------------------------------------------
// Layer 1 projection: d_A = x @ W1   (x: [N,128], W1: [128,32])
// ---------------------------------------------------------------------------
__global__ void __launch_bounds__(128) proj1_kernel(const float* __restrict__ x,
                                                    const float* __restrict__ W) {
    __shared__ float sW[D_FEAT * D_HID];
    for (int i = threadIdx.x; i < D_FEAT * D_HID; i += 128) sW[i] = W[i];
    __syncthreads();

    int n = blockIdx.x * 128 + threadIdx.x;
    if (n >= N_NODES) return;

    float acc[D_HID];
#pragma unroll
    for (int j = 0; j < D_HID; j++) acc[j] = 0.f;

    const float4* xr = reinterpret_cast<const float4*>(x) + (size_t)n * (D_FEAT / 4);
#pragma unroll 4
    for (int k4 = 0; k4 < D_FEAT / 4; k4++) {
        float4 v = xr[k4];
        const float* w0 = &sW[(k4 * 4 + 0) * D_HID];
        const float* w1 = &sW[(k4 * 4 + 1) * D_HID];
        const float* w2 = &sW[(k4 * 4 + 2) * D_HID];
        const float* w3 = &sW[(k4 * 4 + 3) * D_HID];
#pragma unroll
        for (int j = 0; j < D_HID; j++)
            acc[j] += v.x * w0[j] + v.y * w1[j] + v.z * w2[j] + v.w * w3[j];
    }

    float4* out4 = reinterpret_cast<float4*>(d_A) + (size_t)n * (D_HID / 4);
#pragma unroll
    for (int q = 0; q < D_HID / 4; q++)
        out4[q] = make_float4(acc[4 * q], acc[4 * q + 1], acc[4 * q + 2], acc[4 * q + 3]);
}

// ---------------------------------------------------------------------------
// CSR build (coalesced 3-stage scan; count/fill vectorized 4 edges/thread)
// ---------------------------------------------------------------------------
__global__ void __launch_bounds__(256) zero_misc_kernel() {
    int i = blockIdx.x * 256 + threadIdx.x;
    if (i < N_NODES) d_deg[i] = 0;
    if (i < N_GRAPHS * D_HID) d_pool[i] = 0.f;
}

// 4 contiguous edges per thread via int4; 4 independent REDG in flight
__global__ void __launch_bounds__(256) count_kernel(const int* __restrict__ row, int E) {
    int t = blockIdx.x * 256 + threadIdx.x;
    int e = t * 4;
    if (e + 3 < E) {
        int4 r = *reinterpret_cast<const int4*>(row + e);
        atomicAdd(&d_deg[r.x], 1);
        atomicAdd(&d_deg[r.y], 1);
        atomicAdd(&d_deg[r.z], 1);
        atomicAdd(&d_deg[r.w], 1);
    } else {
        for (; e < E; e++) atomicAdd(&d_deg[row[e]], 1);
    }
}

__global__ void __launch_bounds__(SCAN_B) scan1_kernel() {
    __shared__ int sh[SCAN_B];
    int i = blockIdx.x * SCAN_B + threadIdx.x;
    int v = (i < N_NODES) ? d_deg[i] : 0;
    sh[threadIdx.x] = v;
    __syncthreads();
    for (int s = 1; s < SCAN_B; s <<= 1) {
        int t = (threadIdx.x >= s) ? sh[threadIdx.x - s] : 0;
        __syncthreads();
        sh[threadIdx.x] += t;
        __syncthreads();
    }
    if (i < N_NODES) d_off[i] = sh[threadIdx.x] - v;   // exclusive
    if (threadIdx.x == SCAN_B - 1) d_bsum[blockIdx.x] = sh[SCAN_B - 1];
}

__global__ void __launch_bounds__(256) scan2_kernel() {
    __shared__ int sh[256];
    int v = (threadIdx.x < NB_SCAN) ? d_bsum[threadIdx.x] : 0;
    sh[threadIdx.x] = v;
    __syncthreads();
    for (int s = 1; s < 256; s <<= 1) {
        int t = (threadIdx.x >= s) ? sh[threadIdx.x - s] : 0;
        __syncthreads();
        sh[threadIdx.x] += t;
        __syncthreads();
    }
    if (threadIdx.x < NB_SCAN) d_bsum[threadIdx.x] = sh[threadIdx.x] - v;  // exclusive
}

__global__ void __launch_bounds__(SCAN_B) scan3_kernel(int E) {
    int i = blockIdx.x * SCAN_B + threadIdx.x;
    if (i < N_NODES) {
        int o = d_off[i] + d_bsum[blockIdx.x];
        d_off[i] = o;
        d_cur[i] = o;
    }
    if (i == 0) d_off[N_NODES] = E;
}

// 4 contiguous edges per thread: int4 row/col + float4 ew, 4 atomic chains
__global__ void __launch_bounds__(256) fill_kernel(const int* __restrict__ row,
                                                   const int* __restrict__ col,
                                                   const float* __restrict__ ew, int E) {
    int t = blockIdx.x * 256 + threadIdx.x;
    int e = t * 4;
    if (e + 3 < E) {
        int4 r = *reinterpret_cast<const int4*>(row + e);
        int4 c = *reinterpret_cast<const int4*>(col + e);
        float4 w = *reinterpret_cast<const float4*>(ew + e);
        int p0 = atomicAdd(&d_cur[r.x], 1);
        int p1 = atomicAdd(&d_cur[r.y], 1);
        int p2 = atomicAdd(&d_cur[r.z], 1);
        int p3 = atomicAdd(&d_cur[r.w], 1);
        d_pk[p0] = make_float2(__int_as_float(c.x), w.x);
        d_pk[p1] = make_float2(__int_as_float(c.y), w.y);
        d_pk[p2] = make_float2(__int_as_float(c.z), w.z);
        d_pk[p3] = make_float2(__int_as_float(c.w), w.w);
    } else {
        for (; e < E; e++) {
            int pos = atomicAdd(&d_cur[row[e]], 1);
            d_pk[pos] = make_float2(__int_as_float(col[e]), ew[e]);
        }
    }
}

// ---------------------------------------------------------------------------
// Fused SpMM gather: warp per node, 4 edges per LDG.128 (spmm4, fp32).
//   PASS 0: src=d_A, dst=d_B, PROJ (elu(acc+b) @ W)
//   PASS 1: src=d_B, dst=d_A, PROJ
//   PASS 2: src=d_A, fused pool: red.global d_pool[seg[n]] += elu(acc+b)
// ---------------------------------------------------------------------------
template <int PASS, bool PROJ>
__global__ void __launch_bounds__(256) spmm4_kernel(const float* __restrict__ W,
                                                    const float* __restrict__ b,
                                                    const int* __restrict__ seg) {
    const float4* __restrict__ src =
        reinterpret_cast<const float4*>((PASS == 1) ? d_B : d_A);

    __shared__ float sW[D_HID * D_HID];
    __shared__ float sb[D_HID];
    if (PROJ)
        for (int i = threadIdx.x; i < D_HID * D_HID; i += 256) sW[i] = W[i];
    if (threadIdx.x < D_HID) sb[threadIdx.x] = b[threadIdx.x];
    __syncthreads();

    int wid = blockIdx.x * 8 + (threadIdx.x >> 5);
    if (wid >= N_NODES) return;
    int lane = threadIdx.x & 31;
    int s = lane & 7;        // float4 slot within row
    int g = lane >> 3;       // edge group 0..3

    int beg = d_off[wid];
    int end = d_off[wid + 1];

    float ax = 0.f, ay = 0.f, az = 0.f, aw = 0.f;
    int e = beg;

    // 8 edges per iteration: two independent LDG.128 chains in flight
    for (; e + 8 <= end; e += 8) {
        float2 pa = d_pk[e + g];
        float2 pb = d_pk[e + 4 + g];
        float4 va = src[(size_t)__float_as_int(pa.x) * 8 + s];
        float4 vb = src[(size_t)__float_as_int(pb.x) * 8 + s];
        ax += pa.y * va.x; ay += pa.y * va.y; az += pa.y * va.z; aw += pa.y * va.w;
        ax += pb.y * vb.x; ay += pb.y * vb.y; az += pb.y * vb.z; aw += pb.y * vb.w;
    }
    for (; e + 4 <= end; e += 4) {
        float2 p = d_pk[e + g];
        float4 v = src[(size_t)__float_as_int(p.x) * 8 + s];
        ax += p.y * v.x; ay += p.y * v.y; az += p.y * v.z; aw += p.y * v.w;
    }
    int rem = end - e;
    if (rem > 0) {
        float2 p = d_pk[e + (g < rem ? g : 0)];
        float wgt = (g < rem) ? p.y : 0.f;
        float4 v = src[(size_t)__float_as_int(p.x) * 8 + s];
        ax += wgt * v.x; ay += wgt * v.y; az += wgt * v.z; aw += wgt * v.w;
    }

    // reduce the 4 edge-groups
    ax += __shfl_xor_sync(0xffffffffu, ax, 8);
    ay += __shfl_xor_sync(0xffffffffu, ay, 8);
    az += __shfl_xor_sync(0xffffffffu, az, 8);
    aw += __shfl_xor_sync(0xffffffffu, aw, 8);
    ax += __shfl_xor_sync(0xffffffffu, ax, 16);
    ay += __shfl_xor_sync(0xffffffffu, ay, 16);
    az += __shfl_xor_sync(0xffffffffu, az, 16);
    aw += __shfl_xor_sync(0xffffffffu, aw, 16);

    // every lane with slot s now holds full sums of cols 4s..4s+3
    float hv[4];
    hv[0] = elu_f(ax + sb[4 * s + 0]);
    hv[1] = elu_f(ay + sb[4 * s + 1]);
    hv[2] = elu_f(az + sb[4 * s + 2]);
    hv[3] = elu_f(aw + sb[4 * s + 3]);

    if (PROJ) {
        // h_k lives in lane k/4 (lanes 0-7), component k%4 (compile-time index)
        float o = 0.f;
#pragma unroll
        for (int k = 0; k < D_HID; k++) {
            float hk = __shfl_sync(0xffffffffu, hv[k & 3], k >> 2);
            o += hk * sW[k * D_HID + lane];
        }
        float* dst = (PASS == 0) ? d_B : d_A;
        dst[(size_t)wid * D_HID + lane] = o;
    } else {
        // fused global pool: one v4 reduction per slot, group-0 lanes only
        if (g == 0) {
            int gr = seg[wid];
            float* p = &d_pool[gr * D_HID + 4 * s];
            asm volatile("red.global.add.v4.f32 [%0], {%1, %2, %3, %4};"
                         :: "l"(p), "f"(hv[0]), "f"(hv[1]), "f"(hv[2]), "f"(hv[3])
                         : "memory");
        }
    }
}

// ---------------------------------------------------------------------------
// Dense head
// ---------------------------------------------------------------------------
__global__ void __launch_bounds__(64) mlp_kernel(const float* __restrict__ Wd1,
                                                 const float* __restrict__ bd1,
                                                 const float* __restrict__ Wd2,
                                                 const float* __restrict__ bd2,
                                                 const float* __restrict__ Wd3,
                                                 const float* __restrict__ bd3,
                                                 float* __restrict__ out) {
    __shared__ float sW1[32 * 64];
    __shared__ float sW2[64 * 32];
    __shared__ float sW3[32];
    __shared__ float sg[32];
    __shared__ float sh1[64];
    __shared__ float sh2[32];

    int t = threadIdx.x;
    int r = blockIdx.x;
    for (int i = t; i < 32 * 64; i += 64) sW1[i] = Wd1[i];
    for (int i = t; i < 64 * 32; i += 64) sW2[i] = Wd2[i];
    if (t < 32) sW3[t] = Wd3[t];
    if (t < 32) sg[t] = d_pool[r * 32 + t];
    __syncthreads();

    {
        float a = bd1[t];
#pragma unroll
        for (int k = 0; k < 32; k++) a += sg[k] * sW1[k * 64 + t];
        sh1[t] = fmaxf(a, 0.f);
    }
    __syncthreads();

    if (t < 32) {
        float a = bd2[t];
#pragma unroll
        for (int k = 0; k < 64; k++) a += sh1[k] * sW2[k * 32 + t];
        sh2[t] = fmaxf(a, 0.f);
    }
    __syncthreads();

    if (t == 0) {
        float a = bd3[0];
#pragma unroll
        for (int k = 0; k < 32; k++) a += sh2[k] * sW3[k];
        out[r] = 1.f / (1.f + expf(-a));
    }
}

// ---------------------------------------------------------------------------
// Launch
// ---------------------------------------------------------------------------
extern "C" void kernel_launch(void* const* d_in, const int* in_sizes, int n_in,
                              void* d_out, int out_size) {
    const float* x   = (const float*)d_in[0];
    const int*   ei  = (const int*)d_in[1];
    const float* ew  = (const float*)d_in[2];
    const int*   seg = (const int*)d_in[3];
    const float* W1  = (const float*)d_in[4];
    const float* b1  = (const float*)d_in[5];
    const float* W2  = (const float*)d_in[6];
    const float* b2  = (const float*)d_in[7];
    const float* W3  = (const float*)d_in[8];
    const float* b3  = (const float*)d_in[9];
    const float* Wd1 = (const float*)d_in[10];
    const float* bd1 = (const float*)d_in[11];
    const float* Wd2 = (const float*)d_in[12];
    const float* bd2 = (const float*)d_in[13];
    const float* Wd3 = (const float*)d_in[14];
    const float* bd3 = (const float*)d_in[15];
    float* out = (float*)d_out;

    int E = in_sizes[2];
    const int* row = ei;
    const int* col = ei + E;

    const int e4grid = ((E + 3) / 4 + 255) / 256;   // 4 edges/thread kernels
    const int ggrid = (N_NODES + 7) / 8;            // warp-per-node

    // CSR build (+ zero the pool table)
    zero_misc_kernel<<<(N_NODES + 255) / 256, 256>>>();
    count_kernel<<<e4grid, 256>>>(row, E);
    scan1_kernel<<<NB_SCAN, SCAN_B>>>();
    scan2_kernel<<<1, 256>>>();
    scan3_kernel<<<NB_SCAN, SCAN_B>>>(E);
    fill_kernel<<<e4grid, 256>>>(row, col, ew, E);

    // Layer 1 projection
    proj1_kernel<<<(N_NODES + 127) / 128, 128>>>(x, W1);

    // Fused SpMM + elu + projection chain; pass 2 fuses the global pool
    spmm4_kernel<0, true><<<ggrid, 256>>>(W2, b1, nullptr);   // A -> B
    spmm4_kernel<1, true><<<ggrid, 256>>>(W3, b2, nullptr);   // B -> A
    spmm4_kernel<2, false><<<ggrid, 256>>>(nullptr, b3, seg); // A -> pool

    // Dense head
    mlp_kernel<<<N_GRAPHS, 64>>>(Wd1, bd1, Wd2, bd2, Wd3, bd3, out);
}